// round 5
// baseline (speedup 1.0000x reference)
#include <cuda_runtime.h>
#include <cuda_bf16.h>
#include <cstdint>

// ---------------- problem constants ----------------
#define BATCH   64
#define FEAT    128
#define KDIM    2048
#define NDATA   100000
#define NSAMP   16385               // K+1
#define NPAIR   (BATCH * NSAMP)     // 1,048,640
#define NCE_T_INV (1.0f / 0.07f)
#define M_CONST (16384.0f / 100000.0f)
#define EPS_C   1e-7f

#define NSPLIT  64                  // embed split-K (chunk 32)
#define RBLK    128                 // rows per logits tile
#define NTILE   ((NDATA + RBLK - 1) / RBLK)   // 782
#define SA      136                 // smem row stride (bf16 elems), 272B padded rows

#define NBB     148                 // blocks per bank
#define NB      (2 * NBB)           // 296 blocks = 148 SMs x occ 2
#define GSTRIDE (NBB * 256)
#define GITER   28                  // ceil(NPAIR / GSTRIDE)

// dynamic smem layout (bytes)
#define ABUF_BYTES (RBLK * SA * 2)            // 34816 per A buffer
#define VS_OFF     (2 * ABUF_BYTES)           // 69632
#define ES_OFF     (VS_OFF + BATCH * SA * 2)  // 87040
#define ES_STRIDE  36                         // u32 words per E-stage row (bank 4r+c)
#define SMEM_DYN   (ES_OFF + RBLK * ES_STRIDE * 4)  // 105472

// ---------------- device scratch (zero-init; reset each call) ----------------
__device__ float          g_partial[2][NSPLIT][BATCH * FEAT];
__device__ uint32_t       g_hb[2][BATCH * FEAT / 2];
__device__ __nv_bfloat16  g_E[2][(size_t)NDATA * BATCH];
__device__ double         g_Z[2];
__device__ double         g_L;
__device__ int            g_bars[4];
__device__ int            g_done;

// ---------------- helpers ----------------
__device__ __forceinline__ void ldsm_x4(uint32_t* r, uint32_t addr) {
    asm volatile("ldmatrix.sync.aligned.m8n8.x4.shared.b16 {%0,%1,%2,%3}, [%4];"
                 : "=r"(r[0]), "=r"(r[1]), "=r"(r[2]), "=r"(r[3]) : "r"(addr));
}
__device__ __forceinline__ void mma_bf16(float* c, const uint32_t* a, uint32_t b0, uint32_t b1) {
    asm volatile("mma.sync.aligned.m16n8k16.row.col.f32.bf16.bf16.f32 "
                 "{%0,%1,%2,%3}, {%4,%5,%6,%7}, {%8,%9}, {%0,%1,%2,%3};"
                 : "+f"(c[0]), "+f"(c[1]), "+f"(c[2]), "+f"(c[3])
                 : "r"(a[0]), "r"(a[1]), "r"(a[2]), "r"(a[3]), "r"(b0), "r"(b1));
}
__device__ __forceinline__ uint32_t pack_bf2(float x, float y) {
    __nv_bfloat162 h2 = __floats2bfloat162_rn(x, y);
    return *reinterpret_cast<uint32_t*>(&h2);
}
__device__ __forceinline__ float ld_e_cg(const __nv_bfloat16* p) {
    unsigned short v;
    asm volatile("ld.global.cg.u16 %0, [%1];" : "=h"(v) : "l"(p));
    __nv_bfloat16 b;
    *reinterpret_cast<unsigned short*>(&b) = v;
    return __bfloat162float(b);
}
__device__ __forceinline__ void gbar(int idx) {
    __syncthreads();
    if (threadIdx.x == 0) {
        __threadfence();
        atomicAdd(&g_bars[idx], 1);
        while (*(volatile int*)&g_bars[idx] < NB) __nanosleep(100);
    }
    __syncthreads();
}

// producer: coalesced LDG.128 of 8 rows (one row per warp-instr), fp32->bf16
__device__ __forceinline__ void prod_load(const float* __restrict__ mem, int rb,
                                          int warp, int lane, int roff, float4* pb) {
#pragma unroll
    for (int r = 0; r < 8; r++) {
        int rg = rb + warp * 16 + roff + r;
        rg = rg < NDATA ? rg : NDATA - 1;
        pb[r] = __ldcs(reinterpret_cast<const float4*>(mem + (size_t)rg * FEAT) + lane);
    }
}
__device__ __forceinline__ void prod_store(uint16_t* dst, int warp, int lane,
                                           int roff, const float4* pb) {
#pragma unroll
    for (int r = 0; r < 8; r++) {
        const int row = warp * 16 + roff + r;
        uint2 u;
        u.x = pack_bf2(pb[r].x, pb[r].y);
        u.y = pack_bf2(pb[r].z, pb[r].w);
        *reinterpret_cast<uint2*>(&dst[row * SA + lane * 4]) = u;
    }
}

// ================= the one kernel =================
__global__ __launch_bounds__(256, 2) void k_fused(
    const float* __restrict__ fs, const float* __restrict__ ft,
    const int*   __restrict__ samp,
    const float* __restrict__ ws, const float* __restrict__ bsv,
    const float* __restrict__ wt, const float* __restrict__ btv,
    const float* __restrict__ mem_v1, const float* __restrict__ mem_v2,
    float* __restrict__ out)
{
    extern __shared__ __align__(16) char dsm[];
    __shared__ float s_red[8];
    __shared__ float s_z;

    const int u    = blockIdx.x;
    const int tid  = threadIdx.x;
    const int lane = tid & 31, warp = tid >> 5;

    // ---------------- P0: embed GEMM, split-K fp32 (blocks 0..127) ----------------
    if (u < 2 * NSPLIT) {
        const int which = u >> 6;
        const int split = u & 63;
        const float* feat = which ? ft : fs;
        const float* w    = which ? wt : ws;
        const int k0 = split * 32;

        float* sf = reinterpret_cast<float*>(dsm);              // 64 x 33
        float* sw = sf + BATCH * 33;                            // 128 x 33

        for (int i = tid; i < BATCH * 32; i += 256) {
            int b = i >> 5, kk = i & 31;
            sf[b * 33 + kk] = feat[b * KDIM + k0 + kk];
        }
        for (int i = tid; i < FEAT * 32; i += 256) {
            int d = i >> 5, kk = i & 31;
            sw[d * 33 + kk] = w[d * KDIM + k0 + kk];
        }
        __syncthreads();

        const int d0 = (tid >> 4) * 8, b0 = (tid & 15) * 4;
        float acc[4][8];
#pragma unroll
        for (int i = 0; i < 4; i++)
#pragma unroll
            for (int j = 0; j < 8; j++) acc[i][j] = 0.f;

#pragma unroll 4
        for (int kk = 0; kk < 32; kk++) {
            float fv[4], wv[8];
#pragma unroll
            for (int i = 0; i < 4; i++) fv[i] = sf[(b0 + i) * 33 + kk];
#pragma unroll
            for (int j = 0; j < 8; j++) wv[j] = sw[(d0 + j) * 33 + kk];
#pragma unroll
            for (int i = 0; i < 4; i++)
#pragma unroll
                for (int j = 0; j < 8; j++) acc[i][j] += fv[i] * wv[j];
        }
        float* outp = g_partial[which][split];
#pragma unroll
        for (int i = 0; i < 4; i++)
#pragma unroll
            for (int j = 0; j < 8; j++)
                outp[(b0 + i) * FEAT + d0 + j] = acc[i][j];
    }
    gbar(0);

    // ---------------- P1: reduce splits + bias + l2norm + pack bf16 ----------------
    if (u < 128) {
        const int which = u >> 6;
        const int b     = u & 63;
        const float* bias = which ? btv : bsv;
        float s = 0.f, v = 0.f;
        if (tid < 128) {
            const int d = tid;
#pragma unroll 8
            for (int sp = 0; sp < NSPLIT; sp++)
                s += __ldcg(&g_partial[which][sp][b * FEAT + d]);
            s += bias[d];
            float sq = s * s;
#pragma unroll
            for (int o = 16; o; o >>= 1) sq += __shfl_xor_sync(0xffffffffu, sq, o);
            if ((d & 31) == 0) s_red[d >> 5] = sq;
        }
        __syncthreads();
        if (tid < 128) {
            const float tot = s_red[0] + s_red[1] + s_red[2] + s_red[3];
            v = s * rsqrtf(tot);
            const float vn = __shfl_down_sync(0xffffffffu, v, 1);
            if ((tid & 1) == 0)
                g_hb[which][(b * FEAT + tid) >> 1] = pack_bf2(v, vn);
        }
    }
    gbar(1);

    // ---------------- P2: smem-staged bf16 GEMM + fused exp ----------------
    const int bank = (u >= NBB) ? 1 : 0;
    const int bx = u - bank * NBB;
    {
        const float* __restrict__ mem = bank ? mem_v1 : mem_v2;
        uint16_t* A0 = reinterpret_cast<uint16_t*>(dsm);
        uint16_t* A1 = reinterpret_cast<uint16_t*>(dsm + ABUF_BYTES);
        uint16_t* Vs = reinterpret_cast<uint16_t*>(dsm + VS_OFF);
        uint32_t* Es = reinterpret_cast<uint32_t*>(dsm + ES_OFF);

        // stage V (persistent across tiles)
        for (int i = tid; i < BATCH * 64; i += 256) {
            const int row = i >> 6, c2 = i & 63;
            *reinterpret_cast<uint32_t*>(&Vs[row * SA + c2 * 2]) = __ldcg(&g_hb[bank][i]);
        }

        // prologue: produce first tile into A0
        {
            float4 pb[8];
            prod_load(mem, bx * RBLK, warp, lane, 0, pb);
            prod_store(A0, warp, lane, 0, pb);
            prod_load(mem, bx * RBLK, warp, lane, 8, pb);
            prod_store(A0, warp, lane, 8, pb);
        }
        __syncthreads();

        const uint32_t v_base = (uint32_t)__cvta_generic_to_shared(Vs);
        const int mg = warp & 3, nh = warp >> 2;
        const int lr = lane & 7, q = lane >> 3;
        const int a_r = lr + ((q & 1) << 3);
        const int a_k = (q >> 1) << 3;
        const int b_r = lr + ((q >> 1) << 3);
        const int b_k = (q & 1) << 3;
        uint32_t* Eb = reinterpret_cast<uint32_t*>(g_E[bank]);

        int i = 0;
        for (int tile = bx; tile < NTILE; tile += NBB, i++) {
            uint16_t* cur = (i & 1) ? A1 : A0;
            uint16_t* nxt = (i & 1) ? A0 : A1;
            const int r_base = tile * RBLK;
            const int ntile_r = (tile + NBB) * RBLK;
            const bool hn = (tile + NBB) < NTILE;
            const uint32_t a_base = (uint32_t)__cvta_generic_to_shared(cur);

            float acc[2][4][4];
#pragma unroll
            for (int mh = 0; mh < 2; mh++)
#pragma unroll
                for (int nf = 0; nf < 4; nf++)
#pragma unroll
                    for (int e = 0; e < 4; e++) acc[mh][nf][e] = 0.f;

            float4 pb[8];
            if (hn) prod_load(mem, ntile_r, warp, lane, 0, pb);   // in flight over ks 0..3

#pragma unroll
            for (int ks = 0; ks < 8; ks++) {
                const int k0 = ks * 16;
                uint32_t a0[4], a1[4], bb0[4], bb1[4];
                ldsm_x4(a0, a_base + (uint32_t)((mg * 32 + a_r) * SA + k0 + a_k) * 2u);
                ldsm_x4(a1, a_base + (uint32_t)((mg * 32 + 16 + a_r) * SA + k0 + a_k) * 2u);
                ldsm_x4(bb0, v_base + (uint32_t)((nh * 32 + b_r) * SA + k0 + b_k) * 2u);
                ldsm_x4(bb1, v_base + (uint32_t)((nh * 32 + 16 + b_r) * SA + k0 + b_k) * 2u);
                mma_bf16(acc[0][0], a0, bb0[0], bb0[1]);
                mma_bf16(acc[0][1], a0, bb0[2], bb0[3]);
                mma_bf16(acc[0][2], a0, bb1[0], bb1[1]);
                mma_bf16(acc[0][3], a0, bb1[2], bb1[3]);
                mma_bf16(acc[1][0], a1, bb0[0], bb0[1]);
                mma_bf16(acc[1][1], a1, bb0[2], bb0[3]);
                mma_bf16(acc[1][2], a1, bb1[0], bb1[1]);
                mma_bf16(acc[1][3], a1, bb1[2], bb1[3]);
                if (ks == 3 && hn) {
                    prod_store(nxt, warp, lane, 0, pb);
                    prod_load(mem, ntile_r, warp, lane, 8, pb);   // in flight over ks 4..7
                }
            }
            if (hn) prod_store(nxt, warp, lane, 8, pb);
            __syncthreads();   // A(cur) reads done; nxt fully written

            // stage exp(acc) -> Es  (conflict-free STS.32: bank = 4r + c)
            const int er = lane >> 2, ec = lane & 3;
#pragma unroll
            for (int mh = 0; mh < 2; mh++)
#pragma unroll
                for (int nf = 0; nf < 4; nf++) {
                    const int row_l = mg * 32 + mh * 16 + er;
                    const int colw  = nh * 16 + nf * 4 + ec;
                    Es[row_l * ES_STRIDE + colw] =
                        pack_bf2(__expf(acc[mh][nf][0] * NCE_T_INV),
                                 __expf(acc[mh][nf][1] * NCE_T_INV));
                    Es[(row_l + 8) * ES_STRIDE + colw] =
                        pack_bf2(__expf(acc[mh][nf][2] * NCE_T_INV),
                                 __expf(acc[mh][nf][3] * NCE_T_INV));
                }
            __syncthreads();

            // coalesced write-out: LDS.128 + STG.128 (4 rows x 128B per warp-instr)
#pragma unroll
            for (int it = 0; it < 4; it++) {
                const int idx = it * 256 + tid;          // 16B chunk id
                const int row = idx >> 3, c16 = idx & 7;
                const uint4 v = *reinterpret_cast<const uint4*>(&Es[row * ES_STRIDE + c16 * 4]);
                const int rg = r_base + row;
                if (rg < NDATA)
                    *reinterpret_cast<uint4*>(&Eb[(size_t)rg * 32 + c16 * 4]) = v;
            }
        }
    }
    gbar(2);

    // ---------------- P3: gather into registers + Z ----------------
    const int pbase = bx * 256 + tid;
    float gv[GITER];
    {
#pragma unroll
        for (int i = 0; i < GITER; i++) {
            const int p = pbase + i * GSTRIDE;
            gv[i] = 0.f;
            if (p < NPAIR) {
                const int s = __ldg(&samp[p]);
                const int b = p / NSAMP;
                gv[i] = ld_e_cg(&g_E[bank][(size_t)s * BATCH + b]);
            }
        }
        float lsum = 0.f;
#pragma unroll
        for (int i = 0; i < GITER; i++) lsum += gv[i];
#pragma unroll
        for (int o = 16; o; o >>= 1) lsum += __shfl_xor_sync(0xffffffffu, lsum, o);
        if ((tid & 31) == 0) s_red[tid >> 5] = lsum;
        __syncthreads();
        if (tid == 0) {
            double tot = 0.0;
#pragma unroll
            for (int i = 0; i < 8; i++) tot += (double)s_red[i];
            atomicAdd(&g_Z[bank], tot);
        }
    }
    gbar(3);

    // ---------------- P4: loss from registers (batched logs) ----------------
    {
        if (tid == 0) {
            const double Zv = *(volatile double*)&g_Z[bank];
            s_z = (float)(Zv * ((double)NDATA / (double)NPAIR));
        }
        __syncthreads();
        const float zinv = 1.0f / s_z;

        float lsum = 0.f;
        float pn = 1.f, pd = 1.f;
#pragma unroll
        for (int i = 0; i < GITER; i++) {
            const int p = pbase + i * GSTRIDE;
            if (p < NPAIR) {
                const float x = gv[i] * zinv;
                const int b = p / NSAMP;
                const bool pos = (p - b * NSAMP) == 0;
                pn *= pos ? x : M_CONST;
                pd *= x + M_CONST + EPS_C;
            }
            if (i == 13 || i == GITER - 1) {
                lsum += __logf(pn / pd);
                pn = 1.f; pd = 1.f;
            }
        }
#pragma unroll
        for (int o = 16; o; o >>= 1) lsum += __shfl_xor_sync(0xffffffffu, lsum, o);
        __syncthreads();
        if ((tid & 31) == 0) s_red[tid >> 5] = lsum;
        __syncthreads();
        if (tid == 0) {
            double tot = 0.0;
#pragma unroll
            for (int i = 0; i < 8; i++) tot += (double)s_red[i];
            atomicAdd(&g_L, tot);
            __threadfence();
            const int v = atomicAdd(&g_done, 1);
            if (v == NB - 1) {
                const double L = *(volatile double*)&g_L;
                out[0] = (float)(-L / (double)BATCH);
                g_Z[0] = 0.0; g_Z[1] = 0.0; g_L = 0.0;
                g_bars[0] = g_bars[1] = g_bars[2] = g_bars[3] = 0;
                g_done = 0;
                __threadfence();
            }
        }
    }
}

// ---------------- launcher ----------------
extern "C" void kernel_launch(void* const* d_in, const int* in_sizes, int n_in,
                              void* d_out, int out_size) {
    const float* feat_s     = (const float*)d_in[0];
    const float* feat_t     = (const float*)d_in[1];
    // d_in[2] = idx (unused; positives already in sample_idx[:,0])
    const int*   sample_idx = (const int*)d_in[3];
    const float* w_s        = (const float*)d_in[4];
    const float* b_s        = (const float*)d_in[5];
    const float* w_t        = (const float*)d_in[6];
    const float* b_t        = (const float*)d_in[7];
    const float* mem_v1     = (const float*)d_in[8];
    const float* mem_v2     = (const float*)d_in[9];
    float* out = (float*)d_out;

    cudaFuncSetAttribute(k_fused, cudaFuncAttributeMaxDynamicSharedMemorySize, SMEM_DYN);
    k_fused<<<NB, 256, SMEM_DYN>>>(feat_s, feat_t, sample_idx,
                                   w_s, b_s, w_t, b_t, mem_v1, mem_v2, out);
}

// round 6
// speedup vs baseline: 1.0562x; 1.0562x over previous
#include <cuda_runtime.h>
#include <cuda_bf16.h>
#include <cstdint>

// ---------------- problem constants ----------------
#define BATCH   64
#define FEAT    128
#define KDIM    2048
#define NDATA   100000
#define NSAMP   16385               // K+1
#define NPAIR   (BATCH * NSAMP)     // 1,048,640
#define NCE_T_INV (1.0f / 0.07f)
#define M_CONST (16384.0f / 100000.0f)
#define EPS_C   1e-7f

#define NSPLIT  64                  // embed split-K (chunk 32)
#define RBLK    128                 // rows per logits tile
#define NTILE   ((NDATA + RBLK - 1) / RBLK)   // 782
#define SA      136                 // smem row stride (bf16 elems)

#define NPRE    128                 // k_pre blocks
#define NPB     296                 // k_post blocks per bank
#define NPOST   (2 * NPB)           // 592 = 148 SMs x 4
#define GSTRIDE (NPB * 256)         // 75776
#define GITER   14                  // ceil(NPAIR / GSTRIDE)

// ---------------- device scratch (zero-init; reset each call) ----------------
__device__ float          g_partial[2][NSPLIT][BATCH * FEAT];
__device__ uint32_t       g_hb[2][BATCH * FEAT / 2];
__device__ __nv_bfloat16  g_E[2][(size_t)NDATA * BATCH];
__device__ double         g_Z[2];
__device__ double         g_L;
__device__ int            g_bars[2];
__device__ int            g_done;

// ---------------- helpers ----------------
__device__ __forceinline__ void ldsm_x4(uint32_t* r, uint32_t addr) {
    asm volatile("ldmatrix.sync.aligned.m8n8.x4.shared.b16 {%0,%1,%2,%3}, [%4];"
                 : "=r"(r[0]), "=r"(r[1]), "=r"(r[2]), "=r"(r[3]) : "r"(addr));
}
__device__ __forceinline__ void mma_bf16(float* c, const uint32_t* a, uint32_t b0, uint32_t b1) {
    asm volatile("mma.sync.aligned.m16n8k16.row.col.f32.bf16.bf16.f32 "
                 "{%0,%1,%2,%3}, {%4,%5,%6,%7}, {%8,%9}, {%0,%1,%2,%3};"
                 : "+f"(c[0]), "+f"(c[1]), "+f"(c[2]), "+f"(c[3])
                 : "r"(a[0]), "r"(a[1]), "r"(a[2]), "r"(a[3]), "r"(b0), "r"(b1));
}
__device__ __forceinline__ uint32_t pack_bf2(float x, float y) {
    __nv_bfloat162 h2 = __floats2bfloat162_rn(x, y);
    return *reinterpret_cast<uint32_t*>(&h2);
}
__device__ __forceinline__ float ld_e_cg(const __nv_bfloat16* p) {
    unsigned short v;
    asm volatile("ld.global.cg.u16 %0, [%1];" : "=h"(v) : "l"(p));
    __nv_bfloat16 b;
    *reinterpret_cast<unsigned short*>(&b) = v;
    return __bfloat162float(b);
}
__device__ __forceinline__ void gbar(int idx, int count) {
    __syncthreads();
    if (threadIdx.x == 0) {
        __threadfence();
        atomicAdd(&g_bars[idx], 1);
        while (*(volatile int*)&g_bars[idx] < count) __nanosleep(100);
    }
    __syncthreads();
}

// ================= K_PRE: embed GEMM + l2norm (128 blocks, 1 grid-bar) =================
__global__ __launch_bounds__(256) void k_pre(
    const float* __restrict__ fs, const float* __restrict__ ft,
    const float* __restrict__ ws, const float* __restrict__ bsv,
    const float* __restrict__ wt, const float* __restrict__ btv)
{
    __shared__ float sf[BATCH * 33];
    __shared__ float sw[FEAT * 33];
    __shared__ float s_red[4];

    const int u   = blockIdx.x;
    const int tid = threadIdx.x;

    // ---- embed split-K ----
    {
        const int which = u >> 6;
        const int split = u & 63;
        const float* feat = which ? ft : fs;
        const float* w    = which ? wt : ws;
        const int k0 = split * 32;

        for (int i = tid; i < BATCH * 32; i += 256) {
            int b = i >> 5, kk = i & 31;
            sf[b * 33 + kk] = feat[b * KDIM + k0 + kk];
        }
        for (int i = tid; i < FEAT * 32; i += 256) {
            int d = i >> 5, kk = i & 31;
            sw[d * 33 + kk] = w[d * KDIM + k0 + kk];
        }
        __syncthreads();

        const int d0 = (tid >> 4) * 8, b0 = (tid & 15) * 4;
        float acc[4][8];
#pragma unroll
        for (int i = 0; i < 4; i++)
#pragma unroll
            for (int j = 0; j < 8; j++) acc[i][j] = 0.f;

#pragma unroll 4
        for (int kk = 0; kk < 32; kk++) {
            float fv[4], wv[8];
#pragma unroll
            for (int i = 0; i < 4; i++) fv[i] = sf[(b0 + i) * 33 + kk];
#pragma unroll
            for (int j = 0; j < 8; j++) wv[j] = sw[(d0 + j) * 33 + kk];
#pragma unroll
            for (int i = 0; i < 4; i++)
#pragma unroll
                for (int j = 0; j < 8; j++) acc[i][j] += fv[i] * wv[j];
        }
        float* outp = g_partial[which][split];
#pragma unroll
        for (int i = 0; i < 4; i++)
#pragma unroll
            for (int j = 0; j < 8; j++)
                outp[(b0 + i) * FEAT + d0 + j] = acc[i][j];
    }
    gbar(0, NPRE);

    // ---- reduce splits + bias + l2norm + pack bf16 ----
    {
        const int which = u >> 6;
        const int b     = u & 63;
        const float* bias = which ? btv : bsv;
        float s = 0.f;
        if (tid < 128) {
            const int d = tid;
#pragma unroll 8
            for (int sp = 0; sp < NSPLIT; sp++)
                s += __ldcg(&g_partial[which][sp][b * FEAT + d]);
            s += bias[d];
            float sq = s * s;
#pragma unroll
            for (int o = 16; o; o >>= 1) sq += __shfl_xor_sync(0xffffffffu, sq, o);
            if ((d & 31) == 0) s_red[d >> 5] = sq;
        }
        __syncthreads();
        if (tid < 128) {
            const float tot = s_red[0] + s_red[1] + s_red[2] + s_red[3];
            const float v = s * rsqrtf(tot);
            const float vn = __shfl_down_sync(0xffffffffu, v, 1);
            if ((tid & 1) == 0)
                g_hb[which][(b * FEAT + tid) >> 1] = pack_bf2(v, vn);
        }
    }
}

// ================= K_LOGITS: dense bf16 GEMM + fused exp (high occupancy) =================
// bank 0: v = hs vs mem_v2 ; bank 1: v = ht vs mem_v1
__global__ __launch_bounds__(256) void k_logits(const float* __restrict__ mem_v1,
                                                const float* __restrict__ mem_v2) {
    const int bank = blockIdx.y;
    const float* __restrict__ mem = bank ? mem_v1 : mem_v2;
    const int r_base = blockIdx.x * RBLK;

    __shared__ __nv_bfloat16 Vs[BATCH * SA];

    const int tid = threadIdx.x;
    for (int i = tid; i < BATCH * 64; i += 256) {
        const int row = i >> 6, c2 = i & 63;
        *reinterpret_cast<uint32_t*>(&Vs[row * SA + c2 * 2]) = g_hb[bank][i];
    }
    __syncthreads();

    const uint32_t v_base = (uint32_t)__cvta_generic_to_shared(Vs);
    const int lane = tid & 31, warp = tid >> 5;
    const int lr = lane & 7, q = lane >> 3;

    const int row0 = r_base + warp * 16 + (lane >> 2);
    const int row1 = row0 + 8;
    const int rc0 = row0 < NDATA ? row0 : NDATA - 1;
    const int rc1 = row1 < NDATA ? row1 : NDATA - 1;
    const float* p0 = mem + (size_t)rc0 * FEAT + (lane & 3) * 2;
    const float* p1 = mem + (size_t)rc1 * FEAT + (lane & 3) * 2;

    const int b_row = lr + ((q >> 1) << 3);
    const int b_kh  = (q & 1) << 3;

    float acc[8][4];
#pragma unroll
    for (int f = 0; f < 8; f++)
#pragma unroll
        for (int e = 0; e < 4; e++) acc[f][e] = 0.f;

    float2 buf[2][4];
#define LOADK(s, ks) {                                                          \
        buf[s][0] = __ldcs(reinterpret_cast<const float2*>(p0 + (ks) * 16));      \
        buf[s][1] = __ldcs(reinterpret_cast<const float2*>(p1 + (ks) * 16));      \
        buf[s][2] = __ldcs(reinterpret_cast<const float2*>(p0 + (ks) * 16 + 8));  \
        buf[s][3] = __ldcs(reinterpret_cast<const float2*>(p1 + (ks) * 16 + 8)); }

    LOADK(0, 0);
    LOADK(1, 1);

#pragma unroll
    for (int ks = 0; ks < 8; ks++) {
        const int s = ks & 1;
        uint32_t a[4];
#pragma unroll
        for (int e = 0; e < 4; e++) a[e] = pack_bf2(buf[s][e].x, buf[s][e].y);
        if (ks < 6) LOADK(s, ks + 2);
        const int k0 = ks * 16;
#pragma unroll
        for (int nt = 0; nt < 4; nt++) {
            uint32_t bb[4];
            ldsm_x4(bb, v_base + (uint32_t)((nt * 16 + b_row) * SA + k0 + b_kh) * 2u);
            mma_bf16(acc[nt * 2 + 0], a, bb[0], bb[1]);
            mma_bf16(acc[nt * 2 + 1], a, bb[2], bb[3]);
        }
    }
#undef LOADK

    // epilogue: exp(logit/T) -> bf16 E[r][b]
    uint32_t* Eb = reinterpret_cast<uint32_t*>(g_E[bank]);
    const int cbase = (lane & 3) * 2;
#pragma unroll
    for (int f = 0; f < 8; f++) {
        const int c = (f >> 1) * 16 + (f & 1) * 8 + cbase;
        if (row0 < NDATA)
            Eb[(size_t)row0 * (BATCH / 2) + (c >> 1)] =
                pack_bf2(__expf(acc[f][0] * NCE_T_INV), __expf(acc[f][1] * NCE_T_INV));
        if (row1 < NDATA)
            Eb[(size_t)row1 * (BATCH / 2) + (c >> 1)] =
                pack_bf2(__expf(acc[f][2] * NCE_T_INV), __expf(acc[f][3] * NCE_T_INV));
    }
}

// ================= K_POST: gather + Z | grid-bar | loss + final (592 blocks, occ 4) =================
__global__ __launch_bounds__(256, 4) void k_post(const int* __restrict__ samp,
                                                 float* __restrict__ out) {
    __shared__ float s_red[8];
    __shared__ float s_z;

    const int u    = blockIdx.x;
    const int tid  = threadIdx.x;
    const int bank = (u >= NPB) ? 1 : 0;
    const int bx   = u - bank * NPB;
    const int pbase = bx * 256 + tid;

    // ---- gather into registers + Z ----
    float gv[GITER];
#pragma unroll
    for (int i = 0; i < GITER; i++) {
        const int p = pbase + i * GSTRIDE;
        gv[i] = 0.f;
        if (p < NPAIR) {
            const int s = __ldg(&samp[p]);
            const int b = p / NSAMP;
            gv[i] = ld_e_cg(&g_E[bank][(size_t)s * BATCH + b]);
        }
    }
    {
        float lsum = 0.f;
#pragma unroll
        for (int i = 0; i < GITER; i++) lsum += gv[i];
#pragma unroll
        for (int o = 16; o; o >>= 1) lsum += __shfl_xor_sync(0xffffffffu, lsum, o);
        if ((tid & 31) == 0) s_red[tid >> 5] = lsum;
        __syncthreads();
        if (tid == 0) {
            double tot = 0.0;
#pragma unroll
            for (int i = 0; i < 8; i++) tot += (double)s_red[i];
            atomicAdd(&g_Z[bank], tot);
        }
    }
    gbar(1, NPOST);

    // ---- loss from registers (batched logs: two groups of 7) ----
    if (tid == 0) {
        const double Zv = *(volatile double*)&g_Z[bank];
        s_z = (float)(Zv * ((double)NDATA / (double)NPAIR));
    }
    __syncthreads();
    const float zinv = 1.0f / s_z;

    float lsum = 0.f;
    float pn = 1.f, pd = 1.f;
#pragma unroll
    for (int i = 0; i < GITER; i++) {
        const int p = pbase + i * GSTRIDE;
        if (p < NPAIR) {
            const float x = gv[i] * zinv;
            const int b = p / NSAMP;
            const bool pos = (p - b * NSAMP) == 0;
            pn *= pos ? x : M_CONST;
            pd *= x + M_CONST + EPS_C;
        }
        if (i == 6 || i == GITER - 1) {
            lsum += __logf(pn / pd);
            pn = 1.f; pd = 1.f;
        }
    }
#pragma unroll
    for (int o = 16; o; o >>= 1) lsum += __shfl_xor_sync(0xffffffffu, lsum, o);
    __syncthreads();
    if ((tid & 31) == 0) s_red[tid >> 5] = lsum;
    __syncthreads();
    if (tid == 0) {
        double tot = 0.0;
#pragma unroll
        for (int i = 0; i < 8; i++) tot += (double)s_red[i];
        atomicAdd(&g_L, tot);
        __threadfence();
        const int v = atomicAdd(&g_done, 1);
        if (v == NPOST - 1) {
            const double L = *(volatile double*)&g_L;
            out[0] = (float)(-L / (double)BATCH);
            // reset all state for the next graph replay
            g_Z[0] = 0.0; g_Z[1] = 0.0; g_L = 0.0;
            g_bars[0] = 0; g_bars[1] = 0;
            g_done = 0;
            __threadfence();
        }
    }
}

// ---------------- launcher: 3 kernels ----------------
extern "C" void kernel_launch(void* const* d_in, const int* in_sizes, int n_in,
                              void* d_out, int out_size) {
    const float* feat_s     = (const float*)d_in[0];
    const float* feat_t     = (const float*)d_in[1];
    // d_in[2] = idx (unused; positives already in sample_idx[:,0])
    const int*   sample_idx = (const int*)d_in[3];
    const float* w_s        = (const float*)d_in[4];
    const float* b_s        = (const float*)d_in[5];
    const float* w_t        = (const float*)d_in[6];
    const float* b_t        = (const float*)d_in[7];
    const float* mem_v1     = (const float*)d_in[8];
    const float* mem_v2     = (const float*)d_in[9];
    float* out = (float*)d_out;

    k_pre<<<NPRE, 256>>>(feat_s, feat_t, w_s, b_s, w_t, b_t);
    k_logits<<<dim3(NTILE, 2), 256>>>(mem_v1, mem_v2);
    k_post<<<NPOST, 256>>>(sample_idx, out);
}

// round 7
// speedup vs baseline: 1.0780x; 1.0207x over previous
#include <cuda_runtime.h>
#include <cuda_bf16.h>
#include <cstdint>

// ---------------- problem constants ----------------
#define BATCH   64
#define FEAT    128
#define KDIM    2048
#define NDATA   100000
#define NSAMP   16385               // K+1
#define NPAIR   (BATCH * NSAMP)     // 1,048,640
#define NCE_T_INV (1.0f / 0.07f)
#define M_CONST (16384.0f / 100000.0f)
#define EPS_C   1e-7f

#define ESPLIT  32                  // embed k-splits per side (chunk 64)
#define KCH     64                  // embed k-chunk
#define RBLK    128                 // rows per logits tile
#define NTILE   ((NDATA + RBLK - 1) / RBLK)   // 782
#define SA      136                 // smem row stride (bf16 elems)

#define NBB     148                 // blocks per bank
#define NB      (2 * NBB)           // 296 blocks = 148 SMs x occ 2
#define GSTRIDE (NBB * 256)         // 37888
#define GITER   28                  // ceil(NPAIR / GSTRIDE)

#define SMEM_DYN ((128 + 64) * SA * 2)   // 52224 B: Ws[128][SA] + Fs[64][SA] (P0) / Vs (P2)

// ---------------- device scratch (zero-init; reset each call) ----------------
__device__ float          g_partial[2][ESPLIT][FEAT * BATCH];   // [d*64+b], 2 MB
__device__ uint32_t       g_hb[2][BATCH * FEAT / 2];
__device__ __nv_bfloat16  g_E[2][(size_t)NDATA * BATCH];
__device__ float          g_Zp[2][NBB];
__device__ float          g_Lp[NB];
__device__ int            g_bars[5][8];

// ---------------- helpers ----------------
__device__ __forceinline__ void ldsm_x4(uint32_t* r, uint32_t addr) {
    asm volatile("ldmatrix.sync.aligned.m8n8.x4.shared.b16 {%0,%1,%2,%3}, [%4];"
                 : "=r"(r[0]), "=r"(r[1]), "=r"(r[2]), "=r"(r[3]) : "r"(addr));
}
__device__ __forceinline__ void mma_bf16(float* c, const uint32_t* a, uint32_t b0, uint32_t b1) {
    asm volatile("mma.sync.aligned.m16n8k16.row.col.f32.bf16.bf16.f32 "
                 "{%0,%1,%2,%3}, {%4,%5,%6,%7}, {%8,%9}, {%0,%1,%2,%3};"
                 : "+f"(c[0]), "+f"(c[1]), "+f"(c[2]), "+f"(c[3])
                 : "r"(a[0]), "r"(a[1]), "r"(a[2]), "r"(a[3]), "r"(b0), "r"(b1));
}
__device__ __forceinline__ uint32_t pack_bf2(float x, float y) {
    __nv_bfloat162 h2 = __floats2bfloat162_rn(x, y);
    return *reinterpret_cast<uint32_t*>(&h2);
}
__device__ __forceinline__ float ld_e_cg(const __nv_bfloat16* p) {
    unsigned short v;
    asm volatile("ld.global.cg.u16 %0, [%1];" : "=h"(v) : "l"(p));
    __nv_bfloat16 b;
    *reinterpret_cast<unsigned short*>(&b) = v;
    return __bfloat162float(b);
}
__device__ __forceinline__ int bar_sum(int idx) {
    volatile int* s = g_bars[idx];
    int t = 0;
#pragma unroll
    for (int i = 0; i < 8; i++) t += s[i];
    return t;
}
// sharded grid barrier: 8 counter slots -> ~8x less same-address serialization
__device__ __forceinline__ void gbar(int idx, int u) {
    __syncthreads();
    if (threadIdx.x == 0) {
        __threadfence();
        atomicAdd(&g_bars[idx][u & 7], 1);
        while (bar_sum(idx) < NB) __nanosleep(64);
    }
    __syncthreads();
}

// ================= the one kernel =================
__global__ __launch_bounds__(256, 2) void k_fused(
    const float* __restrict__ fs, const float* __restrict__ ft,
    const int*   __restrict__ samp,
    const float* __restrict__ ws, const float* __restrict__ bsv,
    const float* __restrict__ wt, const float* __restrict__ btv,
    const float* __restrict__ mem_v1, const float* __restrict__ mem_v2,
    float* __restrict__ out)
{
    extern __shared__ __align__(16) char dsm[];
    __shared__ float  s_red[8];
    __shared__ double s_dd[8];
    __shared__ float  s_z;

    const int u    = blockIdx.x;
    const int tid  = threadIdx.x;
    const int lane = tid & 31, warp = tid >> 5;
    const int lr = lane & 7, q = lane >> 3;

    // ---------------- P0: embed GEMM via MMA, split-K (64 blocks) ----------------
    if (u < 2 * ESPLIT) {
        const int which = u >> 5;
        const int split = u & 31;
        const int k0 = split * KCH;
        const float* W = which ? wt : ws;
        const float* F = which ? ft : fs;

        uint16_t* Ws = reinterpret_cast<uint16_t*>(dsm);          // 128 x SA
        uint16_t* Fs = Ws + 128 * SA;                             // 64 x SA

        // load W chunk [128 x 64] fp32 -> bf16 (2048 float4, 8/thread)
#pragma unroll
        for (int j = 0; j < 8; j++) {
            const int i = tid + j * 256;
            const int row = i >> 4, c4 = i & 15;
            const float4 v = __ldg(reinterpret_cast<const float4*>(W + row * KDIM + k0) + c4);
            uint2 p;
            p.x = pack_bf2(v.x, v.y);
            p.y = pack_bf2(v.z, v.w);
            *reinterpret_cast<uint2*>(&Ws[row * SA + c4 * 4]) = p;
        }
        // load F chunk [64 x 64] (1024 float4, 4/thread)
#pragma unroll
        for (int j = 0; j < 4; j++) {
            const int i = tid + j * 256;
            const int row = i >> 4, c4 = i & 15;
            const float4 v = __ldg(reinterpret_cast<const float4*>(F + row * KDIM + k0) + c4);
            uint2 p;
            p.x = pack_bf2(v.x, v.y);
            p.y = pack_bf2(v.z, v.w);
            *reinterpret_cast<uint2*>(&Fs[row * SA + c4 * 4]) = p;
        }
        __syncthreads();

        const uint32_t a_base = (uint32_t)__cvta_generic_to_shared(Ws);
        const uint32_t b_base = (uint32_t)__cvta_generic_to_shared(Fs);
        const int mg = warp & 3, nh = warp >> 2;     // m128 = 4x32, n64 = 2x32
        const int a_r = lr + ((q & 1) << 3), a_k = (q >> 1) << 3;
        const int b_r = lr + ((q >> 1) << 3), b_k = (q & 1) << 3;

        float acc[2][4][4];
#pragma unroll
        for (int mh = 0; mh < 2; mh++)
#pragma unroll
            for (int nf = 0; nf < 4; nf++)
#pragma unroll
                for (int e = 0; e < 4; e++) acc[mh][nf][e] = 0.f;

#pragma unroll
        for (int ks = 0; ks < 4; ks++) {
            const int kk = ks * 16;
            uint32_t a0[4], a1[4], bb0[4], bb1[4];
            ldsm_x4(a0, a_base + (uint32_t)((mg * 32 + a_r) * SA + kk + a_k) * 2u);
            ldsm_x4(a1, a_base + (uint32_t)((mg * 32 + 16 + a_r) * SA + kk + a_k) * 2u);
            ldsm_x4(bb0, b_base + (uint32_t)((nh * 32 + b_r) * SA + kk + b_k) * 2u);
            ldsm_x4(bb1, b_base + (uint32_t)((nh * 32 + 16 + b_r) * SA + kk + b_k) * 2u);
            mma_bf16(acc[0][0], a0, bb0[0], bb0[1]);
            mma_bf16(acc[0][1], a0, bb0[2], bb0[3]);
            mma_bf16(acc[0][2], a0, bb1[0], bb1[1]);
            mma_bf16(acc[0][3], a0, bb1[2], bb1[3]);
            mma_bf16(acc[1][0], a1, bb0[0], bb0[1]);
            mma_bf16(acc[1][1], a1, bb0[2], bb0[3]);
            mma_bf16(acc[1][2], a1, bb1[0], bb1[1]);
            mma_bf16(acc[1][3], a1, bb1[2], bb1[3]);
        }

        // store fp32 partials, layout [d*64 + b] (adjacent b -> STG.64)
        float* outp = g_partial[which][split];
        const int er = lane >> 2, ec = lane & 3;
#pragma unroll
        for (int mh = 0; mh < 2; mh++)
#pragma unroll
            for (int nf = 0; nf < 4; nf++) {
                const int rd = mg * 32 + mh * 16 + er;
                const int cb = nh * 32 + nf * 8 + ec * 2;
                float2 v0 = make_float2(acc[mh][nf][0], acc[mh][nf][1]);
                float2 v1 = make_float2(acc[mh][nf][2], acc[mh][nf][3]);
                *reinterpret_cast<float2*>(&outp[rd * BATCH + cb]) = v0;
                *reinterpret_cast<float2*>(&outp[(rd + 8) * BATCH + cb]) = v1;
            }
    }
    gbar(0, u);

    // ---------------- P1: reduce 32 splits + bias + l2norm + pack bf16 (128 blocks) ----------------
    if (u < 128) {
        const int which = u >> 6;
        const int b     = u & 63;
        const float* bias = which ? btv : bsv;
        float s = 0.f;
        if (tid < 128) {
            const int d = tid;
#pragma unroll 8
            for (int sp = 0; sp < ESPLIT; sp++)
                s += __ldcg(&g_partial[which][sp][d * BATCH + b]);
            s += bias[d];
            float sq = s * s;
#pragma unroll
            for (int o = 16; o; o >>= 1) sq += __shfl_xor_sync(0xffffffffu, sq, o);
            if ((tid & 31) == 0) s_red[tid >> 5] = sq;
        }
        __syncthreads();
        if (tid < 128) {
            const float tot = s_red[0] + s_red[1] + s_red[2] + s_red[3];
            const float v = s * rsqrtf(tot);
            const float vn = __shfl_down_sync(0xffffffffu, v, 1);
            if ((tid & 1) == 0)
                g_hb[which][(b * FEAT + tid) >> 1] = pack_bf2(v, vn);
        }
    }
    gbar(1, u);

    // ---------------- P2: dense logits GEMM + fused exp (R4 front-batched) ----------------
    const int bank = (u >= NBB) ? 1 : 0;
    const int bx = u - bank * NBB;
    {
        const float* __restrict__ mem = bank ? mem_v1 : mem_v2;
        uint16_t* Vs = reinterpret_cast<uint16_t*>(dsm);          // 64 x SA

        for (int i = tid; i < BATCH * 64; i += 256) {
            const int row = i >> 6, c2 = i & 63;
            *reinterpret_cast<uint32_t*>(&Vs[row * SA + c2 * 2]) = __ldcg(&g_hb[bank][i]);
        }
        __syncthreads();

        const uint32_t v_base = (uint32_t)__cvta_generic_to_shared(Vs);
        const int b_row = lr + ((q >> 1) << 3);
        const int b_kh  = (q & 1) << 3;
        uint32_t* Eb = reinterpret_cast<uint32_t*>(g_E[bank]);

        for (int tile = bx; tile < NTILE; tile += NBB) {
            const int r_base = tile * RBLK;
            const int row0 = r_base + warp * 16 + (lane >> 2);
            const int row1 = row0 + 8;
            const int rc0 = row0 < NDATA ? row0 : NDATA - 1;
            const int rc1 = row1 < NDATA ? row1 : NDATA - 1;
            const float* p0 = mem + (size_t)rc0 * FEAT + (lane & 3) * 2;
            const float* p1 = mem + (size_t)rc1 * FEAT + (lane & 3) * 2;

            // front-batch: 32 independent LDG.64 per thread
            float2 rbuf[32];
#pragma unroll
            for (int ks = 0; ks < 8; ks++) {
                rbuf[ks * 4 + 0] = __ldcs(reinterpret_cast<const float2*>(p0 + ks * 16));
                rbuf[ks * 4 + 1] = __ldcs(reinterpret_cast<const float2*>(p1 + ks * 16));
                rbuf[ks * 4 + 2] = __ldcs(reinterpret_cast<const float2*>(p0 + ks * 16 + 8));
                rbuf[ks * 4 + 3] = __ldcs(reinterpret_cast<const float2*>(p1 + ks * 16 + 8));
            }

            float acc[8][4];
#pragma unroll
            for (int f = 0; f < 8; f++)
#pragma unroll
                for (int e = 0; e < 4; e++) acc[f][e] = 0.f;

#pragma unroll
            for (int ks = 0; ks < 8; ks++) {
                uint32_t a[4];
#pragma unroll
                for (int e = 0; e < 4; e++)
                    a[e] = pack_bf2(rbuf[ks * 4 + e].x, rbuf[ks * 4 + e].y);
                const int k0 = ks * 16;
#pragma unroll
                for (int nt = 0; nt < 4; nt++) {
                    uint32_t bb[4];
                    ldsm_x4(bb, v_base + (uint32_t)((nt * 16 + b_row) * SA + k0 + b_kh) * 2u);
                    mma_bf16(acc[nt * 2 + 0], a, bb[0], bb[1]);
                    mma_bf16(acc[nt * 2 + 1], a, bb[2], bb[3]);
                }
            }

            const int cbase = (lane & 3) * 2;
#pragma unroll
            for (int f = 0; f < 8; f++) {
                const int c = (f >> 1) * 16 + (f & 1) * 8 + cbase;
                if (row0 < NDATA)
                    Eb[(size_t)row0 * (BATCH / 2) + (c >> 1)] =
                        pack_bf2(__expf(acc[f][0] * NCE_T_INV), __expf(acc[f][1] * NCE_T_INV));
                if (row1 < NDATA)
                    Eb[(size_t)row1 * (BATCH / 2) + (c >> 1)] =
                        pack_bf2(__expf(acc[f][2] * NCE_T_INV), __expf(acc[f][3] * NCE_T_INV));
            }
        }
    }
    gbar(2, u);

    // ---------------- P3: gather into registers + per-block Z slot ----------------
    const int pbase = bx * 256 + tid;
    float gv[GITER];
    {
#pragma unroll
        for (int i = 0; i < GITER; i++) {
            const int p = pbase + i * GSTRIDE;
            gv[i] = 0.f;
            if (p < NPAIR) {
                const int s = __ldg(&samp[p]);
                const int b = p / NSAMP;
                gv[i] = ld_e_cg(&g_E[bank][(size_t)s * BATCH + b]);
            }
        }
        float lsum = 0.f;
#pragma unroll
        for (int i = 0; i < GITER; i++) lsum += gv[i];
#pragma unroll
        for (int o = 16; o; o >>= 1) lsum += __shfl_xor_sync(0xffffffffu, lsum, o);
        if ((tid & 31) == 0) s_red[tid >> 5] = lsum;
        __syncthreads();
        if (tid == 0) {
            double tot = 0.0;
#pragma unroll
            for (int i = 0; i < 8; i++) tot += (double)s_red[i];
            g_Zp[bank][bx] = (float)tot;
        }
    }
    gbar(3, u);

    // each block reduces its bank's 148 Z slots (deterministic order)
    {
        float zv = (tid < NBB) ? *(volatile float*)&g_Zp[bank][tid] : 0.f;
#pragma unroll
        for (int o = 16; o; o >>= 1) zv += __shfl_xor_sync(0xffffffffu, zv, o);
        if (lane == 0) s_red[warp] = zv;
        __syncthreads();
        if (tid == 0) {
            float zt = 0.f;
#pragma unroll
            for (int i = 0; i < 8; i++) zt += s_red[i];
            s_z = (float)((double)zt * ((double)NDATA / (double)NPAIR));
        }
        __syncthreads();
    }

    // ---------------- P4: loss from registers (batched logs) -> per-block L slot ----------------
    {
        const float zinv = 1.0f / s_z;
        float lsum = 0.f;
        float pn = 1.f, pd = 1.f;
#pragma unroll
        for (int i = 0; i < GITER; i++) {
            const int p = pbase + i * GSTRIDE;
            if (p < NPAIR) {
                const float x = gv[i] * zinv;
                const int b = p / NSAMP;
                const bool pos = (p - b * NSAMP) == 0;
                pn *= pos ? x : M_CONST;
                pd *= x + M_CONST + EPS_C;
            }
            if (i == 13 || i == GITER - 1) {
                lsum += __logf(pn / pd);
                pn = 1.f; pd = 1.f;
            }
        }
#pragma unroll
        for (int o = 16; o; o >>= 1) lsum += __shfl_xor_sync(0xffffffffu, lsum, o);
        __syncthreads();
        if ((tid & 31) == 0) s_red[tid >> 5] = lsum;
        __syncthreads();
        if (tid == 0) {
            double tot = 0.0;
#pragma unroll
            for (int i = 0; i < 8; i++) tot += (double)s_red[i];
            g_Lp[u] = (float)tot;
            __threadfence();
            atomicAdd(&g_bars[4][u & 7], 1);
        }
    }

    // ---------------- block 0: finalize + reset ----------------
    if (u == 0) {
        if (tid == 0) {
            while (bar_sum(4) < NB) __nanosleep(64);
        }
        __syncthreads();
        double s = 0.0;
        if (tid < NB) s = (double)*(volatile float*)&g_Lp[tid];
        if (tid < NB - 256) s += (double)*(volatile float*)&g_Lp[tid + 256];
#pragma unroll
        for (int o = 16; o; o >>= 1) s += __shfl_down_sync(0xffffffffu, s, o);
        if (lane == 0) s_dd[warp] = s;
        __syncthreads();
        if (tid == 0) {
            double t = 0.0;
#pragma unroll
            for (int i = 0; i < 8; i++) t += s_dd[i];
            out[0] = (float)(-t / (double)BATCH);
        }
        // reset barrier slots for next replay
        if (tid < 40) g_bars[tid >> 3][tid & 7] = 0;
        __threadfence();
    }
}

// ---------------- launcher ----------------
extern "C" void kernel_launch(void* const* d_in, const int* in_sizes, int n_in,
                              void* d_out, int out_size) {
    const float* feat_s     = (const float*)d_in[0];
    const float* feat_t     = (const float*)d_in[1];
    // d_in[2] = idx (unused; positives already in sample_idx[:,0])
    const int*   sample_idx = (const int*)d_in[3];
    const float* w_s        = (const float*)d_in[4];
    const float* b_s        = (const float*)d_in[5];
    const float* w_t        = (const float*)d_in[6];
    const float* b_t        = (const float*)d_in[7];
    const float* mem_v1     = (const float*)d_in[8];
    const float* mem_v2     = (const float*)d_in[9];
    float* out = (float*)d_out;

    cudaFuncSetAttribute(k_fused, cudaFuncAttributeMaxDynamicSharedMemorySize, SMEM_DYN);
    k_fused<<<NB, 256, SMEM_DYN>>>(feat_s, feat_t, sample_idx,
                                   w_s, b_s, w_t, b_t, mem_v1, mem_v2, out);
}